// round 16
// baseline (speedup 1.0000x reference)
#include <cuda_runtime.h>
#include <cuda_bf16.h>

// NSLoss persistent grid-stride kernel + L2 evict_last via createpolicy/cache_hint.
// loss = -(1/n) * sum_i [ log_sigmoid(<emb_i, W[label_i]>)
//                         + sum_k log_sigmoid(-<emb_i, W[negs_ik]>) ]
// Inputs: y_hat f32[N] (unused), emb f32[N,128], weights f32[1e6,128],
// label i32[N], negs i32[N,10]. Output: f32 scalar.
//
// R14 evidence: timed replays (16.9us) beat cold-cache ncu (23.4us) -> natural
// partial L2 retention across graph replays. Working set ~93MB < 126MB L2.
// This round biases retention with evict_last policy on the gather loads,
// using the cache_hint form (policy operand) which ptxas accepts on v4.f32.
// Structure otherwise identical to the 16.9us R12 winner.

#define D 128
#define NUM_SAMPLED 10
#define NROWS (NUM_SAMPLED + 1)
#define THREADS 256
#define WARPS_PER_BLOCK (THREADS / 32)
#define CTAS_PER_SM 4
#define NUM_SMS 148
#define GRID_BLOCKS (NUM_SMS * CTAS_PER_SM)   /* 592 */
#define NUM_NODES 1000000

__device__ double g_acc = 0.0;
__device__ unsigned int g_arrived = 0;

__device__ __forceinline__ float log_sigmoid_f(float x) {
    return fminf(x, 0.0f) - log1pf(__expf(-fabsf(x)));
}

__device__ __forceinline__ unsigned long long mk_evict_last_policy() {
    unsigned long long pol;
    asm volatile("createpolicy.fractional.L2::evict_last.b64 %0, 1.0;" : "=l"(pol));
    return pol;
}

__device__ __forceinline__ float4 ld_persist_f4(const float4* p, unsigned long long pol) {
    float4 v;
    asm volatile("ld.global.nc.L2::cache_hint.v4.f32 {%0,%1,%2,%3}, [%4], %5;"
                 : "=f"(v.x), "=f"(v.y), "=f"(v.z), "=f"(v.w)
                 : "l"(p), "l"(pol));
    return v;
}

__global__ __launch_bounds__(THREADS, CTAS_PER_SM)
void nsloss_persist_kernel(const float* __restrict__ emb,
                           const float* __restrict__ weights,
                           const int* __restrict__ label,
                           const int* __restrict__ negs,
                           float* __restrict__ out,
                           int n) {
    const int lane = threadIdx.x & 31;
    const int warp_in_blk = threadIdx.x >> 5;
    const int warp_gid = (blockIdx.x * THREADS + threadIdx.x) >> 5;
    const int warp_stride = (GRID_BLOCKS * THREADS) >> 5;   // 4736 warps

    const unsigned long long pol = mk_evict_last_policy();
    float acc_total = 0.0f;   // lane-uniform accumulation across iterations

    for (int i = warp_gid; i < n; i += warp_stride) {
        // ---- indices: lane 0 -> label, lanes 1..10 -> negs ----
        int my_idx = 0;
        if (lane == 0)                my_idx = label[i];
        else if (lane <= NUM_SAMPLED) my_idx = negs[i * NUM_SAMPLED + (lane - 1)];
        my_idx = min(max(my_idx, 0), NUM_NODES - 1);

        // ---- all loads batched, all marked L2-persisting ----
        const float4 e =
            ld_persist_f4(reinterpret_cast<const float4*>(emb + (size_t)i * D) + lane, pol);
        float4 w[NROWS];
        #pragma unroll
        for (int k = 0; k < NROWS; ++k) {
            int row = __shfl_sync(0xffffffffu, my_idx, k);
            w[k] = ld_persist_f4(
                reinterpret_cast<const float4*>(weights + (size_t)row * D) + lane, pol);
        }

        // ---- 11 independent partial dots ----
        float d[NROWS];
        #pragma unroll
        for (int k = 0; k < NROWS; ++k)
            d[k] = e.x * w[k].x + e.y * w[k].y + e.z * w[k].z + e.w * w[k].w;

        // ---- butterfly interleaved across all 11 dots (ILP hides SHFL lat) ----
        #pragma unroll
        for (int off = 16; off > 0; off >>= 1) {
            #pragma unroll
            for (int k = 0; k < NROWS; ++k)
                d[k] += __shfl_xor_sync(0xffffffffu, d[k], off);
        }

        // ---- lane k evaluates sample-component k (1 log-sigmoid per lane) ----
        float mydot = 0.0f;
        #pragma unroll
        for (int k = 0; k < NROWS; ++k)
            if (lane == k) mydot = d[k];
        float contrib = 0.0f;
        if (lane < NROWS) {
            float s = (lane == 0) ? mydot : -mydot;
            contrib = log_sigmoid_f(s);
        }
        #pragma unroll
        for (int off = 16; off > 0; off >>= 1)
            contrib += __shfl_xor_sync(0xffffffffu, contrib, off);
        acc_total += contrib;   // lane-uniform
    }

    // ---- one block reduction + one global atomic per CTA ----
    __shared__ float warp_sums[WARPS_PER_BLOCK];
    __shared__ bool is_last;
    if (lane == 0) warp_sums[warp_in_blk] = acc_total;
    __syncthreads();

    if (threadIdx.x == 0) {
        float s = 0.0f;
        #pragma unroll
        for (int wi = 0; wi < WARPS_PER_BLOCK; ++wi) s += warp_sums[wi];
        atomicAdd(&g_acc, (double)s);
        __threadfence();
        unsigned int prev = atomicAdd(&g_arrived, 1u);
        is_last = (prev == gridDim.x - 1);
    }
    __syncthreads();

    // Last block finalizes: write output, reset state for next graph replay.
    if (is_last && threadIdx.x == 0) {
        double total = g_acc;
        out[0] = (float)(-total / (double)n);
        g_acc = 0.0;
        g_arrived = 0u;
        __threadfence();
    }
}

extern "C" void kernel_launch(void* const* d_in, const int* in_sizes, int n_in,
                              void* d_out, int out_size) {
    const float* emb     = (const float*)d_in[1];
    const float* weights = (const float*)d_in[2];
    const int*   label   = (const int*)d_in[3];
    const int*   negs    = (const int*)d_in[4];
    float* out = (float*)d_out;

    const int n = in_sizes[0];              // N from y_hat length

    nsloss_persist_kernel<<<GRID_BLOCKS, THREADS>>>(emb, weights, label, negs, out, n);
}

// round 17
// speedup vs baseline: 1.0616x; 1.0616x over previous
#include <cuda_runtime.h>
#include <cuda_bf16.h>

// NSLoss persistent grid-stride kernel (R14 winner, reverted from the
// evict_last experiment which regressed 16.9 -> 18.2us).
// loss = -(1/n) * sum_i [ log_sigmoid(<emb_i, W[label_i]>)
//                         + sum_k log_sigmoid(-<emb_i, W[negs_ik]>) ]
// Inputs: y_hat f32[N] (unused), emb f32[N,128], weights f32[1e6,128],
// label i32[N], negs i32[N,10]. Output: f32 scalar.
//
// Persistent grid (4 CTAs/SM x 148 SMs): no wave-boundary queue drains,
// per-warp accumulation across iterations, one block reduction + one global
// atomic per CTA. Plain LDG: natural L2 LRU retention across graph replays
// outperformed both evict_last forms (R11 flat, R15 regression).

#define D 128
#define NUM_SAMPLED 10
#define NROWS (NUM_SAMPLED + 1)
#define THREADS 256
#define WARPS_PER_BLOCK (THREADS / 32)
#define CTAS_PER_SM 4
#define NUM_SMS 148
#define GRID_BLOCKS (NUM_SMS * CTAS_PER_SM)   /* 592 */
#define NUM_NODES 1000000

__device__ double g_acc = 0.0;
__device__ unsigned int g_arrived = 0;

__device__ __forceinline__ float log_sigmoid_f(float x) {
    return fminf(x, 0.0f) - log1pf(__expf(-fabsf(x)));
}

__global__ __launch_bounds__(THREADS, CTAS_PER_SM)
void nsloss_persist_kernel(const float* __restrict__ emb,
                           const float* __restrict__ weights,
                           const int* __restrict__ label,
                           const int* __restrict__ negs,
                           float* __restrict__ out,
                           int n) {
    const int lane = threadIdx.x & 31;
    const int warp_in_blk = threadIdx.x >> 5;
    const int warp_gid = (blockIdx.x * THREADS + threadIdx.x) >> 5;
    const int warp_stride = (GRID_BLOCKS * THREADS) >> 5;   // 4736 warps

    float acc_total = 0.0f;   // lane-uniform accumulation across iterations

    for (int i = warp_gid; i < n; i += warp_stride) {
        // ---- indices: lane 0 -> label, lanes 1..10 -> negs ----
        int my_idx = 0;
        if (lane == 0)                my_idx = label[i];
        else if (lane <= NUM_SAMPLED) my_idx = negs[i * NUM_SAMPLED + (lane - 1)];
        my_idx = min(max(my_idx, 0), NUM_NODES - 1);

        // ---- all loads batched: emb (coalesced 512B) + 11 gathers in flight ----
        const float4 e = reinterpret_cast<const float4*>(emb + (size_t)i * D)[lane];
        float4 w[NROWS];
        #pragma unroll
        for (int k = 0; k < NROWS; ++k) {
            int row = __shfl_sync(0xffffffffu, my_idx, k);
            w[k] = reinterpret_cast<const float4*>(weights + (size_t)row * D)[lane];
        }

        // ---- 11 independent partial dots ----
        float d[NROWS];
        #pragma unroll
        for (int k = 0; k < NROWS; ++k)
            d[k] = e.x * w[k].x + e.y * w[k].y + e.z * w[k].z + e.w * w[k].w;

        // ---- butterfly interleaved across all 11 dots (ILP hides SHFL lat) ----
        #pragma unroll
        for (int off = 16; off > 0; off >>= 1) {
            #pragma unroll
            for (int k = 0; k < NROWS; ++k)
                d[k] += __shfl_xor_sync(0xffffffffu, d[k], off);
        }

        // ---- lane k evaluates sample-component k (1 log-sigmoid per lane) ----
        float mydot = 0.0f;
        #pragma unroll
        for (int k = 0; k < NROWS; ++k)
            if (lane == k) mydot = d[k];
        float contrib = 0.0f;
        if (lane < NROWS) {
            float s = (lane == 0) ? mydot : -mydot;
            contrib = log_sigmoid_f(s);
        }
        #pragma unroll
        for (int off = 16; off > 0; off >>= 1)
            contrib += __shfl_xor_sync(0xffffffffu, contrib, off);
        acc_total += contrib;   // lane-uniform
    }

    // ---- one block reduction + one global atomic per CTA ----
    __shared__ float warp_sums[WARPS_PER_BLOCK];
    __shared__ bool is_last;
    if (lane == 0) warp_sums[warp_in_blk] = acc_total;
    __syncthreads();

    if (threadIdx.x == 0) {
        float s = 0.0f;
        #pragma unroll
        for (int wi = 0; wi < WARPS_PER_BLOCK; ++wi) s += warp_sums[wi];
        atomicAdd(&g_acc, (double)s);
        __threadfence();
        unsigned int prev = atomicAdd(&g_arrived, 1u);
        is_last = (prev == gridDim.x - 1);
    }
    __syncthreads();

    // Last block finalizes: write output, reset state for next graph replay.
    if (is_last && threadIdx.x == 0) {
        double total = g_acc;
        out[0] = (float)(-total / (double)n);
        g_acc = 0.0;
        g_arrived = 0u;
        __threadfence();
    }
}

extern "C" void kernel_launch(void* const* d_in, const int* in_sizes, int n_in,
                              void* d_out, int out_size) {
    const float* emb     = (const float*)d_in[1];
    const float* weights = (const float*)d_in[2];
    const int*   label   = (const int*)d_in[3];
    const int*   negs    = (const int*)d_in[4];
    float* out = (float*)d_out;

    const int n = in_sizes[0];              // N from y_hat length

    nsloss_persist_kernel<<<GRID_BLOCKS, THREADS>>>(emb, weights, label, negs, out, n);
}